// round 2
// baseline (speedup 1.0000x reference)
#include <cuda_runtime.h>
#include <cstdint>

// Problem: B=32, P=512, S=1024, H=1024, R=256, K=3H=3072
// GEMM: out[M=16384, N=256] = feats[M, 3072] @ W^T[3072, 256] + bias
// feats built on the fly: head=0.5(x0+x1), tail=0.5(x2+x3), head*tail.
//
// Tiling: MT=64 rows/CTA (256 CTAs), full N=256/CTA, BK=32 K-chunk, 256 thr.
// Each thread: 16m x 4n outputs as 32 packed f32x2 accumulators via
// fma.rn.f32x2 (2 FMA/lane/op -> 128 FMA/cyc/SM).

#define THREADS 256

__device__ __forceinline__ void fma2(unsigned long long &d,
                                     const unsigned long long a,
                                     const unsigned long long b) {
    asm("fma.rn.f32x2 %0, %1, %2, %0;" : "+l"(d) : "l"(a), "l"(b));
}

__global__ void __launch_bounds__(THREADS, 2)
gr_fused_gemm_kernel(const int*   __restrict__ pairs32,
                     const float* __restrict__ hidden,
                     const float* __restrict__ Wg,
                     const float* __restrict__ bias,
                     float*       __restrict__ out)
{
    constexpr int H  = 1024;
    constexpr int R  = 256;
    constexpr int K3 = 3072;
    constexpr int MT = 64;
    constexpr int BK = 32;

    extern __shared__ float sm[];
    float* Wt = sm;              // [BK][R]    = 32 KB, Wt[k][r] = W[r][kb+k]
    float* At = sm + BK * R;     // [BK][2*MT] = 16 KB, duplicated pairs {v,v}
    __shared__ int4 sIdx[MT];
    __shared__ int  sIs64;

    const int t    = threadIdx.x;
    const int lane = t & 31;
    const int w    = t >> 5;
    const int wm   = w & 3;      // 16-row m group within the 64-row tile
    const int wn   = w >> 2;     // n half: 0 -> cols [0,128), 1 -> [128,256)

    const int row0 = blockIdx.x * MT;     // global row base (64 | 512 -> one b per CTA)
    const int b    = row0 >> 9;
    const int p0   = row0 & 511;

    // ---- dtype sniff: int64 pairs have all-zero odd 32-bit words
    if (t == 0) {
        int acc = 0;
#pragma unroll
        for (int i = 1; i < 128; i += 2) acc |= pairs32[i];
        sIs64 = (acc == 0);
    }
    __syncthreads();

    if (t < MT) {
        const size_t pidx = (size_t)b * 512 + p0 + t;   // pair index
        if (sIs64) {
            const long long* p64 = reinterpret_cast<const long long*>(pairs32) + pidx * 4;
            sIdx[t] = make_int4((int)p64[0], (int)p64[1], (int)p64[2], (int)p64[3]);
        } else {
            sIdx[t] = reinterpret_cast<const int4*>(pairs32)[pidx];
        }
    }

    const float* hb = hidden + (size_t)b * (size_t)(1024 * 1024);

    // A-fill mapping: 4 threads per m-row, each covers 8 consecutive k
    const int am = t & 63;
    const int ak = (t >> 6) << 3;             // 0, 8, 16, 24
    const float* wrow = Wg + (size_t)t * K3;  // thread t owns W row t

    unsigned long long acc[32];
#pragma unroll
    for (int i = 0; i < 32; ++i) acc[i] = 0ull;

    for (int c = 0; c < K3 / BK; ++c) {
        __syncthreads();

        // ---- stage W chunk: Wt[k][t] = W[t][c*32 + k], k in [0,32)
        {
            const float4* src = reinterpret_cast<const float4*>(wrow + c * BK);
#pragma unroll
            for (int i = 0; i < 8; ++i) {
                float4 v = src[i];
                Wt[(i * 4 + 0) * R + t] = v.x;
                Wt[(i * 4 + 1) * R + t] = v.y;
                Wt[(i * 4 + 2) * R + t] = v.z;
                Wt[(i * 4 + 3) * R + t] = v.w;
            }
        }

        // ---- stage A chunk (fused gather + feature construction)
        {
            const int s  = c >> 5;                    // 0=head, 1=tail, 2=head*tail
            const int hk = ((c & 31) << 5) + ak;      // offset within H
            const int4 id = sIdx[am];
            float v[8];
            if (s == 0) {
                const float4* q0 = reinterpret_cast<const float4*>(hb + (size_t)id.x * H + hk);
                const float4* q1 = reinterpret_cast<const float4*>(hb + (size_t)id.y * H + hk);
                float4 a0 = q0[0], a1 = q0[1], c0 = q1[0], c1 = q1[1];
                v[0] = 0.5f * (a0.x + c0.x); v[1] = 0.5f * (a0.y + c0.y);
                v[2] = 0.5f * (a0.z + c0.z); v[3] = 0.5f * (a0.w + c0.w);
                v[4] = 0.5f * (a1.x + c1.x); v[5] = 0.5f * (a1.y + c1.y);
                v[6] = 0.5f * (a1.z + c1.z); v[7] = 0.5f * (a1.w + c1.w);
            } else if (s == 1) {
                const float4* q0 = reinterpret_cast<const float4*>(hb + (size_t)id.z * H + hk);
                const float4* q1 = reinterpret_cast<const float4*>(hb + (size_t)id.w * H + hk);
                float4 a0 = q0[0], a1 = q0[1], c0 = q1[0], c1 = q1[1];
                v[0] = 0.5f * (a0.x + c0.x); v[1] = 0.5f * (a0.y + c0.y);
                v[2] = 0.5f * (a0.z + c0.z); v[3] = 0.5f * (a0.w + c0.w);
                v[4] = 0.5f * (a1.x + c1.x); v[5] = 0.5f * (a1.y + c1.y);
                v[6] = 0.5f * (a1.z + c1.z); v[7] = 0.5f * (a1.w + c1.w);
            } else {
                const float4* q0 = reinterpret_cast<const float4*>(hb + (size_t)id.x * H + hk);
                const float4* q1 = reinterpret_cast<const float4*>(hb + (size_t)id.y * H + hk);
                const float4* q2 = reinterpret_cast<const float4*>(hb + (size_t)id.z * H + hk);
                const float4* q3 = reinterpret_cast<const float4*>(hb + (size_t)id.w * H + hk);
                float4 a0 = q0[0], a1 = q0[1], b0 = q1[0], b1 = q1[1];
                float4 c0 = q2[0], c1 = q2[1], d0 = q3[0], d1 = q3[1];
                v[0] = 0.25f * (a0.x + b0.x) * (c0.x + d0.x);
                v[1] = 0.25f * (a0.y + b0.y) * (c0.y + d0.y);
                v[2] = 0.25f * (a0.z + b0.z) * (c0.z + d0.z);
                v[3] = 0.25f * (a0.w + b0.w) * (c0.w + d0.w);
                v[4] = 0.25f * (a1.x + b1.x) * (c1.x + d1.x);
                v[5] = 0.25f * (a1.y + b1.y) * (c1.y + d1.y);
                v[6] = 0.25f * (a1.z + b1.z) * (c1.z + d1.z);
                v[7] = 0.25f * (a1.w + b1.w) * (c1.w + d1.w);
            }
            // duplicated pairs {v,v} -> compute loads packed f32x2 operands directly
#pragma unroll
            for (int j = 0; j < 8; ++j) {
                *reinterpret_cast<float2*>(At + (ak + j) * (2 * MT) + 2 * am) =
                    make_float2(v[j], v[j]);
            }
        }

        __syncthreads();

        // ---- compute: 32 k-steps, 16m x 2(f32x2-n) FMAs per step
#pragma unroll 4
        for (int k = 0; k < BK; ++k) {
            const ulonglong2* ap =
                reinterpret_cast<const ulonglong2*>(At + k * (2 * MT) + 32 * wm);
            unsigned long long a[16];
#pragma unroll
            for (int q = 0; q < 8; ++q) {
                ulonglong2 aa = ap[q];
                a[2 * q]     = aa.x;
                a[2 * q + 1] = aa.y;
            }
            const unsigned long long* wp =
                reinterpret_cast<const unsigned long long*>(Wt + k * R) + wn * 64 + lane;
            const unsigned long long w0 = wp[0];
            const unsigned long long w1 = wp[32];
#pragma unroll
            for (int mi = 0; mi < 16; ++mi) {
                fma2(acc[2 * mi + 0], a[mi], w0);
                fma2(acc[2 * mi + 1], a[mi], w1);
            }
        }
    }

    // ---- epilogue: add bias, store float2 pairs (coalesced)
    const int nb = wn * 128 + 2 * lane;        // pair 0 at nb; pair 1 at nb+64
    const float2 bv0 = reinterpret_cast<const float2*>(bias)[nb >> 1];
    const float2 bv1 = reinterpret_cast<const float2*>(bias)[(nb + 64) >> 1];
#pragma unroll
    for (int mi = 0; mi < 16; ++mi) {
        const size_t row = (size_t)row0 + wm * 16 + mi;
        float2 r0 = *reinterpret_cast<float2*>(&acc[2 * mi + 0]);
        float2 r1 = *reinterpret_cast<float2*>(&acc[2 * mi + 1]);
        r0.x += bv0.x; r0.y += bv0.y;
        r1.x += bv1.x; r1.y += bv1.y;
        float* orow = out + row * 256;
        *reinterpret_cast<float2*>(orow + nb)      = r0;
        *reinterpret_cast<float2*>(orow + nb + 64) = r1;
    }
}

extern "C" void kernel_launch(void* const* d_in, const int* in_sizes, int n_in,
                              void* d_out, int out_size) {
    (void)in_sizes; (void)n_in; (void)out_size;
    const int*   pairs  = (const int*)  d_in[0];   // [32,512,2,2] int32 or int64 (sniffed)
    const float* hidden = (const float*)d_in[1];   // [32,1024,1024] f32
    const float* W      = (const float*)d_in[2];   // [256,3072] f32
    const float* bias   = (const float*)d_in[3];   // [256] f32
    float*       out    = (float*)d_out;           // [32,512,256] f32

    constexpr int MT = 64;
    constexpr int M  = 32 * 512;
    const size_t smem = (32 * 256 + 32 * 2 * MT) * sizeof(float);  // 49152 B dynamic

    // Opt in to >48KB-total shared (48KB dynamic + 1KB static sIdx).
    static bool attr_set = false;
    if (!attr_set) {
        cudaFuncSetAttribute(gr_fused_gemm_kernel,
                             cudaFuncAttributeMaxDynamicSharedMemorySize,
                             (int)smem);
        attr_set = true;
    }

    gr_fused_gemm_kernel<<<M / MT, THREADS, smem>>>(pairs, hidden, W, bias, out);
}

// round 5
// speedup vs baseline: 2.2989x; 2.2989x over previous
#include <cuda_runtime.h>
#include <cuda_bf16.h>
#include <cstdint>

// B=32, P=512, S=1024, H=1024, R=256, K3=3072
// out[M=16384,256] = feats[M,3072] @ W^T + bias (feats gathered on the fly)
// mma.sync bf16 split-precision: D += Ahi*Bhi + Ahi*Blo + Alo*Bhi (fp32 accum)
// CTA: 128(M) x 256(N), 512 thr (16 warps, 4x4), warp tile 32x64, KC=64.
// NOTE: B is staged [n][k] (k contiguous) == same orientation as A, so BOTH
// operands use non-trans ldmatrix. (.trans was the R4 correctness bug.)

#define THREADS 512

static __device__ __forceinline__ uint32_t smem_u32(const void* p) {
    uint32_t a;
    asm("{ .reg .u64 t; cvta.to.shared.u64 t, %1; cvt.u32.u64 %0, t; }"
        : "=r"(a) : "l"(p));
    return a;
}
static __device__ __forceinline__ void ldsm4(uint32_t* r, uint32_t addr) {
    asm volatile("ldmatrix.sync.aligned.m8n8.x4.shared.b16 {%0,%1,%2,%3}, [%4];"
                 : "=r"(r[0]), "=r"(r[1]), "=r"(r[2]), "=r"(r[3]) : "r"(addr));
}
static __device__ __forceinline__ void mma_bf16(float* d, const uint32_t* a,
                                                const uint32_t* b) {
    asm volatile("mma.sync.aligned.m16n8k16.row.col.f32.bf16.bf16.f32 "
                 "{%0,%1,%2,%3}, {%4,%5,%6,%7}, {%8,%9}, {%0,%1,%2,%3};"
                 : "+f"(d[0]), "+f"(d[1]), "+f"(d[2]), "+f"(d[3])
                 : "r"(a[0]), "r"(a[1]), "r"(a[2]), "r"(a[3]),
                   "r"(b[0]), "r"(b[1]));
}
// split two floats -> packed bf16 hi pair + packed bf16 residual-lo pair
static __device__ __forceinline__ void split2(float a, float b,
                                              uint32_t& hi, uint32_t& lo) {
    __nv_bfloat16 ah = __float2bfloat16(a), bh = __float2bfloat16(b);
    __nv_bfloat16 al = __float2bfloat16(a - __bfloat162float(ah));
    __nv_bfloat16 bl = __float2bfloat16(b - __bfloat162float(bh));
    hi = (uint32_t)__bfloat16_as_ushort(ah) | ((uint32_t)__bfloat16_as_ushort(bh) << 16);
    lo = (uint32_t)__bfloat16_as_ushort(al) | ((uint32_t)__bfloat16_as_ushort(bl) << 16);
}

// SMEM geometry: rows padded to 72 bf16 (144 B, 16B-aligned rows for ldmatrix)
#define LDA 72
#define OFF_AHI 0
#define OFF_ALO (128 * LDA * 2)
#define OFF_BHI (2 * 128 * LDA * 2)
#define OFF_BLO (2 * 128 * LDA * 2 + 256 * LDA * 2)
#define SMEM_BYTES (2 * 128 * LDA * 2 + 2 * 256 * LDA * 2)   // 110592

__global__ void __launch_bounds__(THREADS, 1)
gr_mma_gemm_kernel(const int*   __restrict__ pairs32,
                   const float* __restrict__ hidden,
                   const float* __restrict__ Wg,
                   const float* __restrict__ bias,
                   float*       __restrict__ out)
{
    constexpr int H   = 1024;
    constexpr int K3  = 3072;
    constexpr int MT  = 128;
    constexpr int KC  = 64;
    constexpr int NCH = K3 / KC;   // 48

    extern __shared__ char dsm[];
    const uint32_t smb = smem_u32(dsm);

    __shared__ int4  sIdx[MT];
    __shared__ float sBias[256];
    __shared__ int   sIs64;

    const int t    = threadIdx.x;
    const int lane = t & 31;
    const int w    = t >> 5;
    const int wm   = w & 3;        // m group (32 rows)
    const int wn   = w >> 2;       // n group (64 cols)

    const int row0 = blockIdx.x * MT;
    const int b    = row0 >> 9;
    const int p0   = row0 & 511;

    // pairs dtype sniff: int64 -> all odd 32-bit words zero (indices < 1024)
    if (t == 0) {
        int a = 0;
#pragma unroll
        for (int i = 1; i < 128; i += 2) a |= pairs32[i];
        sIs64 = (a == 0);
    }
    if (t < 256) sBias[t] = bias[t];
    __syncthreads();

    if (t < MT) {
        const size_t pidx = (size_t)b * 512 + p0 + t;
        if (sIs64) {
            const long long* p64 = reinterpret_cast<const long long*>(pairs32) + pidx * 4;
            sIdx[t] = make_int4((int)p64[0], (int)p64[1], (int)p64[2], (int)p64[3]);
        } else {
            sIdx[t] = reinterpret_cast<const int4*>(pairs32)[pidx];
        }
    }
    __syncthreads();

    const float* hb = hidden + (size_t)b * (size_t)(H * 1024);

    // A staging map: 4 thr/row, 16 k each
    const int arow = t >> 2;
    const int akoff = (t & 3) << 4;
    const int4 id = sIdx[arow];
    // B staging map: 2 thr/row, 32 k each
    const int brow = t >> 1;
    const int bkoff = (t & 1) << 5;
    const float* wsrc = Wg + (size_t)brow * K3 + bkoff;

    float acc[2][8][4];
#pragma unroll
    for (int i = 0; i < 2; ++i)
#pragma unroll
        for (int j = 0; j < 8; ++j)
#pragma unroll
            for (int q = 0; q < 4; ++q) acc[i][j][q] = 0.f;

    // ldmatrix lane address components (same pattern for A and B: [row][k])
    const int lr = lane & 15;
    const int lh = (lane >> 4) << 3;
    const uint32_t aAddrBase0 = smb + OFF_AHI + ((wm * 32 + lr) * LDA + lh) * 2;
    const uint32_t bAddrBase0 = smb + OFF_BHI + ((wn * 64 + lr) * LDA + lh) * 2;

    for (int c = 0; c < NCH; ++c) {
        __syncthreads();   // previous chunk's mma reads done

        // ---- stage B (W split hi/lo): row=brow, k in [bkoff, bkoff+32)
        {
            const float4* src = reinterpret_cast<const float4*>(wsrc + c * KC);
            const uint32_t dst = smb + (brow * LDA + bkoff) * 2;
#pragma unroll
            for (int i = 0; i < 8; ++i) {
                float4 v = src[i];
                uint32_t h0, l0, h1, l1;
                split2(v.x, v.y, h0, l0);
                split2(v.z, v.w, h1, l1);
                asm volatile("st.shared.v2.b32 [%0], {%1, %2};"
                             :: "r"(dst + OFF_BHI + i * 8), "r"(h0), "r"(h1));
                asm volatile("st.shared.v2.b32 [%0], {%1, %2};"
                             :: "r"(dst + OFF_BLO + i * 8), "r"(l0), "r"(l1));
            }
        }
        // ---- stage A (gather + feature + split): row=arow, k in [akoff, akoff+16)
        {
            const int s  = c >> 4;                       // 0=head,1=tail,2=prod
            const int hk = ((c & 15) << 6) + akoff;
            const uint32_t dst = smb + (arow * LDA + akoff) * 2;
            const float4* q0 = reinterpret_cast<const float4*>(hb + (size_t)id.x * H + hk);
            const float4* q1 = reinterpret_cast<const float4*>(hb + (size_t)id.y * H + hk);
            const float4* q2 = reinterpret_cast<const float4*>(hb + (size_t)id.z * H + hk);
            const float4* q3 = reinterpret_cast<const float4*>(hb + (size_t)id.w * H + hk);
#pragma unroll
            for (int i = 0; i < 4; ++i) {
                float4 v;
                if (s == 0) {
                    float4 a = q0[i], d = q1[i];
                    v.x = 0.5f*(a.x+d.x); v.y = 0.5f*(a.y+d.y);
                    v.z = 0.5f*(a.z+d.z); v.w = 0.5f*(a.w+d.w);
                } else if (s == 1) {
                    float4 a = q2[i], d = q3[i];
                    v.x = 0.5f*(a.x+d.x); v.y = 0.5f*(a.y+d.y);
                    v.z = 0.5f*(a.z+d.z); v.w = 0.5f*(a.w+d.w);
                } else {
                    float4 a = q0[i], e = q1[i], f = q2[i], g = q3[i];
                    v.x = 0.25f*(a.x+e.x)*(f.x+g.x);
                    v.y = 0.25f*(a.y+e.y)*(f.y+g.y);
                    v.z = 0.25f*(a.z+e.z)*(f.z+g.z);
                    v.w = 0.25f*(a.w+e.w)*(f.w+g.w);
                }
                uint32_t h0, l0, h1, l1;
                split2(v.x, v.y, h0, l0);
                split2(v.z, v.w, h1, l1);
                asm volatile("st.shared.v2.b32 [%0], {%1, %2};"
                             :: "r"(dst + OFF_AHI + i * 8), "r"(h0), "r"(h1));
                asm volatile("st.shared.v2.b32 [%0], {%1, %2};"
                             :: "r"(dst + OFF_ALO + i * 8), "r"(l0), "r"(l1));
            }
        }

        __syncthreads();

        // ---- compute: 4 k16-steps
#pragma unroll
        for (int kk = 0; kk < KC; kk += 16) {
            const uint32_t kb = kk * 2;
            uint32_t a_hi[2][4], b_hi[8][2];
            // A hi frags (2 x m16)
#pragma unroll
            for (int mt = 0; mt < 2; ++mt)
                ldsm4(a_hi[mt], aAddrBase0 + (mt * 16 * LDA) * 2 + kb);
            // B hi frags (4 x n16 -> 8 x n8), non-trans: B is [n][k] like A
#pragma unroll
            for (int p = 0; p < 4; ++p) {
                uint32_t r[4];
                ldsm4(r, bAddrBase0 + (p * 16 * LDA) * 2 + kb);
                b_hi[2*p][0]   = r[0]; b_hi[2*p][1]   = r[2];
                b_hi[2*p+1][0] = r[1]; b_hi[2*p+1][1] = r[3];
            }
            // hi * hi
#pragma unroll
            for (int mt = 0; mt < 2; ++mt)
#pragma unroll
                for (int n8 = 0; n8 < 8; ++n8)
                    mma_bf16(acc[mt][n8], a_hi[mt], b_hi[n8]);
            // lo * hi
            {
                uint32_t a_lo[2][4];
#pragma unroll
                for (int mt = 0; mt < 2; ++mt)
                    ldsm4(a_lo[mt], aAddrBase0 + (OFF_ALO - OFF_AHI) + (mt * 16 * LDA) * 2 + kb);
#pragma unroll
                for (int mt = 0; mt < 2; ++mt)
#pragma unroll
                    for (int n8 = 0; n8 < 8; ++n8)
                        mma_bf16(acc[mt][n8], a_lo[mt], b_hi[n8]);
            }
            // hi * lo (reuse b_hi storage)
#pragma unroll
            for (int p = 0; p < 4; ++p) {
                uint32_t r[4];
                ldsm4(r, bAddrBase0 + (OFF_BLO - OFF_BHI) + (p * 16 * LDA) * 2 + kb);
                b_hi[2*p][0]   = r[0]; b_hi[2*p][1]   = r[2];
                b_hi[2*p+1][0] = r[1]; b_hi[2*p+1][1] = r[3];
            }
#pragma unroll
            for (int mt = 0; mt < 2; ++mt)
#pragma unroll
                for (int n8 = 0; n8 < 8; ++n8)
                    mma_bf16(acc[mt][n8], a_hi[mt], b_hi[n8]);
        }
    }

    // ---- epilogue: add bias, write fp32 results
    const int g  = lane >> 2;
    const int tq = lane & 3;
#pragma unroll
    for (int mt = 0; mt < 2; ++mt) {
        const int r0g = row0 + wm * 32 + mt * 16 + g;
#pragma unroll
        for (int n8 = 0; n8 < 8; ++n8) {
            const int col = wn * 64 + n8 * 8 + tq * 2;
            const float bx = sBias[col], by = sBias[col + 1];
            float* o0 = out + (size_t)r0g * 256 + col;
            float* o1 = o0 + 8 * 256;
            *reinterpret_cast<float2*>(o0) =
                make_float2(acc[mt][n8][0] + bx, acc[mt][n8][1] + by);
            *reinterpret_cast<float2*>(o1) =
                make_float2(acc[mt][n8][2] + bx, acc[mt][n8][3] + by);
        }
    }
}

extern "C" void kernel_launch(void* const* d_in, const int* in_sizes, int n_in,
                              void* d_out, int out_size) {
    (void)in_sizes; (void)n_in; (void)out_size;
    const int*   pairs  = (const int*)  d_in[0];
    const float* hidden = (const float*)d_in[1];
    const float* W      = (const float*)d_in[2];
    const float* bias   = (const float*)d_in[3];
    float*       out    = (float*)d_out;

    constexpr int M = 32 * 512;
    static bool attr_set = false;
    if (!attr_set) {
        cudaFuncSetAttribute(gr_mma_gemm_kernel,
                             cudaFuncAttributeMaxDynamicSharedMemorySize, SMEM_BYTES);
        attr_set = true;
    }
    gr_mma_gemm_kernel<<<M / 128, THREADS, SMEM_BYTES>>>(pairs, hidden, W, bias, out);
}